// round 10
// baseline (speedup 1.0000x reference)
#include <cuda_runtime.h>
#include <cuda_bf16.h>
#include <cstdint>

// out = sum_i | cumsum(x0 - x1)_i |, x = d_in[0] as (2, N) fp32, N = 2^23.
// 293 blocks x 1024 thr, 2 CTAs/SM (112 KB smem each). No global barrier.
//   Phase A (fused): per warp stream 7 tiles: LDG -> diff -> tile warp-scan with
//     running carry -> STS warp-relative inclusive prefix (scan hidden in load shadow).
//   Publish {gen, block aggregate}; decoupled lookback over predecessors -> block
//     prefix (blocks proceed independently; co-resident CTA overlaps phases).
//   Abs pass: 7 LDS.128 + |warpBase + p|; per-block partial.
//   Done-counter finisher: fp64 reduce of 293 partials, write scalar, reset gen.

#define GRID_N   293
#define TPB      1024
#define NWARP    32
#define BLK_F4   7168             // float4 per block (112 KB smem)
#define WARP_F4  224
#define LANE_J   7

typedef unsigned long long ull;

__device__ ull      g_pub[GRID_N];     // {gen_tag:32 | fp32 block aggregate:32}
__device__ float    g_partials[GRID_N];
__device__ unsigned g_done;            // zero-init; reset by finisher
__device__ unsigned g_gen = 1;

__global__ void __launch_bounds__(TPB, 2) emd_scan(const float* __restrict__ x,
                                                   float* __restrict__ out, int N) {
    extern __shared__ float4 spre[];   // warp-relative inclusive prefixes
    __shared__ float    sWarpSums[NWARP];
    __shared__ float    sWarpAcc[NWARP];
    __shared__ float    sBlockPrefix;
    __shared__ unsigned sGen;
    __shared__ unsigned sLast;

    const int  tid  = threadIdx.x;
    const int  w    = tid >> 5;
    const int  lane = tid & 31;
    const int  bid  = blockIdx.x;
    const long tot4 = (long)N / 4;     // 2097152

    if (tid == 0) sGen = *(volatile unsigned*)&g_gen;

    const float4* x0 = (const float4*)x;
    const float4* x1 = (const float4*)(x + N);

    const long blockStart4 = (long)bid * BLK_F4;
    const int  warpLocal4  = w * WARP_F4;

    // ---------------- Phase A: stream + fused tile scans ----------------
    float carry = 0.f;                 // warp-relative running prefix
#pragma unroll
    for (int j = 0; j < LANE_J; ++j) {
        long t4 = blockStart4 + warpLocal4 + j * 32 + lane;
        float4 a, b;
        if (t4 < tot4) { a = x0[t4]; b = x1[t4]; }
        else { a = make_float4(0.f,0.f,0.f,0.f); b = a; }

        float s0 = a.x - b.x;
        float s1 = s0 + (a.y - b.y);
        float s2 = s1 + (a.z - b.z);
        float s3 = s2 + (a.w - b.w);

        float v = s3;                  // warp inclusive scan of lane totals
#pragma unroll
        for (int off = 1; off < 32; off <<= 1) {
            float n = __shfl_up_sync(0xffffffffu, v, off);
            if (lane >= off) v += n;
        }
        float base = carry + (v - s3); // lane-exclusive, warp-relative
        float4 p;
        p.x = base + s0; p.y = base + s1; p.z = base + s2; p.w = base + s3;
        spre[warpLocal4 + j * 32 + lane] = p;
        carry += __shfl_sync(0xffffffffu, v, 31);
    }
    if (lane == 0) sWarpSums[w] = carry;   // warp total
    __syncthreads();

    // ---------------- publish aggregate + decoupled lookback (warp 0) ----------------
    if (w == 0) {
        const unsigned gen = sGen;
        float bs = sWarpSums[lane];
#pragma unroll
        for (int off = 16; off; off >>= 1)
            bs += __shfl_down_sync(0xffffffffu, bs, off);
        if (lane == 0)
            atomicExch(&g_pub[bid], ((ull)gen << 32) | (ull)__float_as_uint(bs));

        float p = 0.f;                 // sum of predecessors' aggregates
        for (int j = lane; j < bid; j += 32) {
            ull pk;
            do { pk = *(volatile ull*)&g_pub[j]; }
            while ((unsigned)(pk >> 32) != gen);
            p += __uint_as_float((unsigned)pk);
        }
#pragma unroll
        for (int off = 16; off; off >>= 1)
            p += __shfl_down_sync(0xffffffffu, p, off);
        if (lane == 0) sBlockPrefix = p;
    }
    __syncthreads();

    float warpBase = sBlockPrefix;
    for (int i = 0; i < w; ++i) warpBase += sWarpSums[i];

    // ---------------- Abs pass: LDS + |warpBase + p| ----------------
    float a0 = 0.f, a1 = 0.f, a2 = 0.f, a3 = 0.f;
#pragma unroll
    for (int j = 0; j < LANE_J; ++j) {
        long t4 = blockStart4 + warpLocal4 + j * 32 + lane;
        if (t4 < tot4) {
            float4 p = spre[warpLocal4 + j * 32 + lane];  // conflict-free LDS.128
            a0 += fabsf(warpBase + p.x);
            a1 += fabsf(warpBase + p.y);
            a2 += fabsf(warpBase + p.z);
            a3 += fabsf(warpBase + p.w);
        }
    }
    float acc = (a0 + a1) + (a2 + a3);
#pragma unroll
    for (int off = 16; off; off >>= 1)
        acc += __shfl_down_sync(0xffffffffu, acc, off);
    if (lane == 0) sWarpAcc[w] = acc;
    __syncthreads();

    // ---------------- completion + finisher ----------------
    if (tid == 0) {
        float bp = 0.f;
#pragma unroll
        for (int i = 0; i < NWARP; ++i) bp += sWarpAcc[i];
        atomicExch(&g_partials[bid], bp);
        __threadfence();
        unsigned old = atomicAdd(&g_done, 1u);
        sLast = (old == GRID_N - 1) ? 1u : 0u;
    }
    __syncthreads();

    if (sLast && w == 0) {
        double p = 0.0;
        for (int i = lane; i < GRID_N; i += 32)
            p += (double)(*(volatile float*)&g_partials[i]);
#pragma unroll
        for (int off = 16; off; off >>= 1)
            p += __shfl_down_sync(0xffffffffu, p, off);
        if (lane == 0) {
            out[0] = (float)p;
            *(volatile unsigned*)&g_done = 0;        // reset for next replay
            __threadfence();
            *(volatile unsigned*)&g_gen = sGen + 1;  // invalidate g_pub tags
        }
    }
}

extern "C" void kernel_launch(void* const* d_in, const int* in_sizes, int n_in,
                              void* d_out, int out_size) {
    const float* x = (const float*)d_in[0];
    int N = in_sizes[0] / 2;               // 8388608
    size_t smem = (size_t)BLK_F4 * sizeof(float4);   // 114688 B

    static bool attr_done = false;
    if (!attr_done) {
        cudaFuncSetAttribute(emd_scan,
                             cudaFuncAttributeMaxDynamicSharedMemorySize,
                             (int)smem);
        attr_done = true;
    }
    emd_scan<<<GRID_N, TPB, smem>>>(x, (float*)d_out, N);
}

// round 11
// speedup vs baseline: 1.1199x; 1.1199x over previous
#include <cuda_runtime.h>
#include <cuda_bf16.h>
#include <cstdint>

// out = sum_i | cumsum(x0 - x1)_i |, x = d_in[0] as (2, N) fp32, N = 2^23.
// 148 blocks (1/SM), 1024 threads, 224 KB smem. R9 structure + __ldcv streaming
// loads (no L1 allocation -> full LTS streaming path) + 2-deep manual prefetch.
//   Phase A: per warp stream 14 tiles: LDCV -> diff -> tile warp-scan with running
//     carry -> STS warp-relative inclusive prefix.
//   ONE grid barrier; block prefix from g_blockSums; abs pass from smem;
//   done-counter finisher reduces 148 partials (fp64), resets counters.

#define GRID_N   148
#define TPB      1024
#define NWARP    32
#define BLK_F4   14336            // float4 per block (224 KB smem)
#define WARP_F4  448
#define LANE_J   14

__device__ float    g_blockSums[GRID_N];
__device__ float    g_partials[GRID_N];
__device__ unsigned g_ctrA;       // barrier counter (reset by finisher)
__device__ unsigned g_done;       // completion counter (reset by finisher)

__global__ void __launch_bounds__(TPB, 1) emd_fused(const float* __restrict__ x,
                                                    float* __restrict__ out, int N) {
    extern __shared__ float4 spre[];          // warp-relative inclusive prefixes
    __shared__ float    sWarpSums[NWARP];
    __shared__ float    sWarpAcc[NWARP];
    __shared__ float    sBlockPrefix;
    __shared__ unsigned sLast;

    const int  tid  = threadIdx.x;
    const int  w    = tid >> 5;
    const int  lane = tid & 31;
    const int  bid  = blockIdx.x;
    const long tot4 = (long)N / 4;            // 2097152

    const float4* x0 = (const float4*)x;
    const float4* x1 = (const float4*)(x + N);

    const long blockStart4 = (long)bid * BLK_F4;
    const int  warpLocal4  = w * WARP_F4;
    const float4 z4 = make_float4(0.f, 0.f, 0.f, 0.f);

    // ---------------- Phase A: stream (LDCV) + fused tile scans ----------------
    float carry = 0.f;                        // warp-relative running prefix

    long t4 = blockStart4 + warpLocal4 + lane;
    float4 a = (t4 < tot4) ? __ldcv(x0 + t4) : z4;
    float4 b = (t4 < tot4) ? __ldcv(x1 + t4) : z4;

#pragma unroll
    for (int j = 0; j < LANE_J; ++j) {
        // prefetch next tile before the dependent scan work
        float4 an = z4, bn = z4;
        if (j + 1 < LANE_J) {
            long n4 = blockStart4 + warpLocal4 + (j + 1) * 32 + lane;
            if (n4 < tot4) { an = __ldcv(x0 + n4); bn = __ldcv(x1 + n4); }
        }

        float s0 = a.x - b.x;
        float s1 = s0 + (a.y - b.y);
        float s2 = s1 + (a.z - b.z);
        float s3 = s2 + (a.w - b.w);

        float v = s3;                         // warp inclusive scan of lane totals
#pragma unroll
        for (int off = 1; off < 32; off <<= 1) {
            float n = __shfl_up_sync(0xffffffffu, v, off);
            if (lane >= off) v += n;
        }
        float base = carry + (v - s3);        // lane-exclusive, warp-relative
        float4 p;
        p.x = base + s0; p.y = base + s1; p.z = base + s2; p.w = base + s3;
        spre[warpLocal4 + j * 32 + lane] = p;
        carry += __shfl_sync(0xffffffffu, v, 31);

        a = an; b = bn;
    }
    if (lane == 0) sWarpSums[w] = carry;      // warp total
    __syncthreads();
    if (tid == 0) {
        float bs = 0.f;
#pragma unroll
        for (int i = 0; i < NWARP; ++i) bs += sWarpSums[i];
        g_blockSums[bid] = bs;
    }

    // ---------------- ONE grid barrier ----------------
    __syncthreads();
    if (tid == 0) {
        __threadfence();
        unsigned v = atomicAdd(&g_ctrA, 1u);
        if (v == GRID_N - 1) atomicAdd(&g_ctrA, 1u);   // release
        while (*(volatile unsigned*)&g_ctrA < GRID_N + 1u) { }
        __threadfence();
    }
    __syncthreads();

    // ---------------- bases ----------------
    if (w == 0) {
        float p = 0.f;
#pragma unroll
        for (int i = lane; i < GRID_N; i += 32)
            if (i < bid) p += g_blockSums[i];
#pragma unroll
        for (int off = 16; off; off >>= 1)
            p += __shfl_down_sync(0xffffffffu, p, off);
        if (lane == 0) sBlockPrefix = p;
    }
    __syncthreads();

    float warpBase = sBlockPrefix;
    for (int i = 0; i < w; ++i) warpBase += sWarpSums[i];

    // ---------------- Abs pass: LDS + |warpBase + p| ----------------
    float a0 = 0.f, a1 = 0.f, a2 = 0.f, a3 = 0.f;
#pragma unroll
    for (int j = 0; j < LANE_J; ++j) {
        long u4 = blockStart4 + warpLocal4 + j * 32 + lane;
        if (u4 < tot4) {
            float4 p = spre[warpLocal4 + j * 32 + lane];  // conflict-free LDS.128
            a0 += fabsf(warpBase + p.x);
            a1 += fabsf(warpBase + p.y);
            a2 += fabsf(warpBase + p.z);
            a3 += fabsf(warpBase + p.w);
        }
    }
    float acc = (a0 + a1) + (a2 + a3);
#pragma unroll
    for (int off = 16; off; off >>= 1)
        acc += __shfl_down_sync(0xffffffffu, acc, off);
    if (lane == 0) sWarpAcc[w] = acc;
    __syncthreads();

    // ---------------- completion + finisher ----------------
    if (tid == 0) {
        float bp = 0.f;
#pragma unroll
        for (int i = 0; i < NWARP; ++i) bp += sWarpAcc[i];
        atomicExch(&g_partials[bid], bp);
        __threadfence();
        unsigned old = atomicAdd(&g_done, 1u);
        sLast = (old == GRID_N - 1) ? 1u : 0u;
    }
    __syncthreads();

    if (sLast && w == 0) {
        double p = 0.0;
        for (int i = lane; i < GRID_N; i += 32)
            p += (double)(*(volatile float*)&g_partials[i]);
#pragma unroll
        for (int off = 16; off; off >>= 1)
            p += __shfl_down_sync(0xffffffffu, p, off);
        if (lane == 0) {
            out[0] = (float)p;
            *(volatile unsigned*)&g_done = 0;   // reset for next graph replay
            __threadfence();
            *(volatile unsigned*)&g_ctrA = 0;   // all blocks are past the barrier
        }
    }
}

extern "C" void kernel_launch(void* const* d_in, const int* in_sizes, int n_in,
                              void* d_out, int out_size) {
    const float* x = (const float*)d_in[0];
    int N = in_sizes[0] / 2;                  // 8388608
    size_t smem = (size_t)BLK_F4 * sizeof(float4);   // 229376 B

    static bool attr_done = false;
    if (!attr_done) {
        cudaFuncSetAttribute(emd_fused,
                             cudaFuncAttributeMaxDynamicSharedMemorySize,
                             (int)smem);
        attr_done = true;
    }
    emd_fused<<<GRID_N, TPB, smem>>>(x, (float*)d_out, N);
}